// round 8
// baseline (speedup 1.0000x reference)
#include <cuda_runtime.h>
#include <cstdint>
#include <cstring>

#define NB 256   // batch
#define NPTS 256 // points per side (N == M)
#define ND 4

// per-batch partials: [0]=sum_xy [1]=sum_nrmx [2]=nx [3]=sum_yx [4]=sum_nrmy0 [5]=ny
__device__ float g_sc[6 * NB];
__device__ int   g_count = 0;

static __device__ __forceinline__ uint64_t dup2(float v) {
    uint64_t r; asm("mov.b64 %0, {%1, %1};" : "=l"(r) : "f"(v)); return r;
}
static __device__ __forceinline__ uint64_t ffma2(uint64_t a, uint64_t b, uint64_t c) {
    uint64_t d; asm("fma.rn.f32x2 %0, %1, %2, %3;" : "=l"(d) : "l"(a), "l"(b), "l"(c)); return d;
}
static __device__ __forceinline__ float2 asf2(uint64_t v) {
    float2 f; memcpy(&f, &v, 8); return f;   // register-pair aliasing, no SASS op
}

__global__ __launch_bounds__(128, 4) void chamfer_kernel(
    const float* __restrict__ target,
    const float* __restrict__ reco,
    const int*   __restrict__ in_pid,
    const int*   __restrict__ out_pid,
    float*       __restrict__ out)
{
    // Full tile (256 pts = 128 pairs), pair-interleaved for f32x2:
    //  sA[p] = { (-2x_e0,-2x_e1) comp0 , comp1 }, sB comp2, comp3
    //  sc[p] = ( ||pt0||^2+pen0 , ||pt1||^2+pen1 )
    __shared__ ulonglong2 sA[NPTS/2], sB[NPTS/2];
    __shared__ uint64_t   sc[NPTS/2];
    __shared__ float4     red[128];
    __shared__ int        s_last;

    const int bid   = blockIdx.x;
    const int b     = bid >> 1;
    const int phase = bid & 1;   // 0: rows=target, tile=reco ; 1: rows=reco, tile=target
    const int t     = threadIdx.x;

    const float* tileSrc = phase == 0 ? reco    : target;
    const int*   tilePid = phase == 0 ? out_pid : in_pid;
    const float* rowSrc  = phase == 0 ? target  : reco;
    const int*   rowPid  = phase == 0 ? in_pid  : out_pid;

    const float4* tile4 = (const float4*)(tileSrc + (size_t)b * NPTS * ND);
    const float4* row4  = (const float4*)(rowSrc  + (size_t)b * NPTS * ND);
    const int*    tpid  = tilePid + b * NPTS;
    const int*    rpid  = rowPid  + b * NPTS;

    // ---- build tile (2 points per thread) ----
    #pragma unroll
    for (int k = 0; k < 2; ++k) {
        int i = t + k * 128;
        float4 v = tile4[i];
        int pid  = tpid[i];
        float n2 = v.x*v.x + v.y*v.y + v.z*v.z + v.w*v.w;
        int pair = i >> 1, lane = i & 1;
        ((float*)sA)[pair*4 + lane]     = -2.0f * v.x;
        ((float*)sA)[pair*4 + 2 + lane] = -2.0f * v.y;
        ((float*)sB)[pair*4 + lane]     = -2.0f * v.z;
        ((float*)sB)[pair*4 + 2 + lane] = -2.0f * v.w;
        ((float*)sc)[i] = n2 + (pid != 0 ? 0.0f : 1e20f);
    }

    // ---- own 2 rows ----
    float4 v0 = row4[t];
    float4 v1 = row4[t + 128];
    const int m0 = (rpid[t] != 0);
    const int m1 = (rpid[t + 128] != 0);
    const float n20 = v0.x*v0.x + v0.y*v0.y + v0.z*v0.z + v0.w*v0.w;
    const float n21 = v1.x*v1.x + v1.y*v1.y + v1.z*v1.z + v1.w*v1.w;

    const uint64_t r0x = dup2(v0.x), r0y = dup2(v0.y), r0z = dup2(v0.z), r0w = dup2(v0.w);
    const uint64_t r1x = dup2(v1.x), r1y = dup2(v1.y), r1z = dup2(v1.z), r1w = dup2(v1.w);

    __syncthreads();

    // ---- main loop: software double-buffered over 128 pair-iters ----
    float d0lo = 3.0e38f, d0hi = 3.0e38f, d1lo = 3.0e38f, d1hi = 3.0e38f;

    ulonglong2 A = sA[0];
    ulonglong2 B = sB[0];
    uint64_t   c = sc[0];

    #pragma unroll 4
    for (int m = 0; m < NPTS/2; ++m) {
        // prefetch next iteration's tile data before consuming current
        int mn = (m + 1) & (NPTS/2 - 1);
        ulonglong2 An = sA[mn];
        ulonglong2 Bn = sB[mn];
        uint64_t   cn = sc[mn];

        uint64_t s0 = ffma2(A.x, r0x, c);
        uint64_t s1 = ffma2(A.x, r1x, c);
        s0 = ffma2(A.y, r0y, s0);
        s1 = ffma2(A.y, r1y, s1);
        s0 = ffma2(B.x, r0z, s0);
        s1 = ffma2(B.x, r1z, s1);
        s0 = ffma2(B.y, r0w, s0);
        s1 = ffma2(B.y, r1w, s1);
        float2 f0 = asf2(s0);
        float2 f1 = asf2(s1);
        d0lo = fminf(d0lo, f0.x); d0hi = fminf(d0hi, f0.y);
        d1lo = fminf(d1lo, f1.x); d1hi = fminf(d1hi, f1.y);

        A = An; B = Bn; c = cn;
    }
    // add row-norm (constant over tile) and clamp cancellation negatives
    float d20 = fmaxf(fminf(d0lo, d0hi) + n20, 0.0f);
    float d21 = fmaxf(fminf(d1lo, d1hi) + n21, 0.0f);

    float sum_min = (m0 ? sqrtf(d20) : 0.0f) + (m1 ? sqrtf(d21) : 0.0f);
    float sum_nrm;
    if (phase == 0)   // sum ||x|| over mask_x
        sum_nrm = (m0 ? sqrtf(n20) : 0.0f) + (m1 ? sqrtf(n21) : 0.0f);
    else              // sum ||y|| over ~mask_y
        sum_nrm = (m0 ? 0.0f : sqrtf(n20)) + (m1 ? 0.0f : sqrtf(n21));
    float cnt = (float)(m0 + m1);     // nx (phase 0) or ny (phase 1)

    // ---- block tree reduction ----
    red[t] = make_float4(sum_min, sum_nrm, cnt, 0.0f);
    __syncthreads();
    #pragma unroll
    for (int s = 64; s > 0; s >>= 1) {
        if (t < s) {
            float4 a = red[t], cc = red[t + s];
            a.x += cc.x; a.y += cc.y; a.z += cc.z;
            red[t] = a;
        }
        __syncthreads();
    }

    if (t == 0) {
        float4 r = red[0];
        g_sc[(phase*3 + 0) * NB + b] = r.x;
        g_sc[(phase*3 + 1) * NB + b] = r.y;
        g_sc[(phase*3 + 2) * NB + b] = r.z;
        __threadfence();
        int old = atomicAdd(&g_count, 1);
        s_last = (old == 2*NB - 1);
    }
    __syncthreads();

    // ---- last block: fused finalize ----
    if (s_last) {
        if (t == 0) { g_count = 0; __threadfence(); }
        __syncthreads();
        float acc0 = 0.0f, acc1 = 0.0f;
        #pragma unroll
        for (int k = 0; k < 2; ++k) {
            int bb = t + k * 128;
            float sum_xy    = __ldcg(&g_sc[0*NB + bb]);
            float sum_nrmx  = __ldcg(&g_sc[1*NB + bb]);
            float fnx       = __ldcg(&g_sc[2*NB + bb]);
            float sum_yx    = __ldcg(&g_sc[3*NB + bb]);
            float sum_nrmy0 = __ldcg(&g_sc[4*NB + bb]);
            float fny       = __ldcg(&g_sc[5*NB + bb]);
            float n_in  = fmaxf(1.0f, fnx);
            float n_out = fmaxf(1.0f, fny);
            float normal = 0.5f * (sum_xy / n_out + sum_yx / n_in);
            float e_nz = (fny == 0.0f) ? (sum_nrmx / n_in)
                       : ((fnx == 0.0f) ? 0.0f : normal);
            float e_z  = sum_nrmy0 / fmaxf(1.0f, (float)NPTS - fny);
            acc0 += e_nz;
            acc1 += e_z;
        }
        red[t] = make_float4(acc0, acc1, 0.0f, 0.0f);
        __syncthreads();
        #pragma unroll
        for (int s = 64; s > 0; s >>= 1) {
            if (t < s) {
                float4 a = red[t], cc = red[t + s];
                a.x += cc.x; a.y += cc.y;
                red[t] = a;
            }
            __syncthreads();
        }
        if (t == 0) {
            out[0] = red[0].x * (1.0f / NB);
            out[1] = red[0].y * (1.0f / NB);
        }
    }
}

extern "C" void kernel_launch(void* const* d_in, const int* in_sizes, int n_in,
                              void* d_out, int out_size)
{
    const float* target  = (const float*)d_in[0];
    const float* reco    = (const float*)d_in[1];
    const int*   in_pid  = (const int*)d_in[2];
    const int*   out_pid = (const int*)d_in[3];
    float* out = (float*)d_out;

    chamfer_kernel<<<2 * NB, 128>>>(target, reco, in_pid, out_pid, out);
}

// round 9
// speedup vs baseline: 1.1728x; 1.1728x over previous
#include <cuda_runtime.h>
#include <cstdint>
#include <cstring>

#define NB 256   // batch
#define NPTS 256 // points per side (N == M)
#define ND 4

// per-batch partials: [0]=sum_xy [1]=sum_nrmx [2]=nx [3]=sum_yx [4]=sum_nrmy0 [5]=ny
__device__ float g_sc[6 * NB];
__device__ int   g_count = 0;

static __device__ __forceinline__ uint64_t dup2(float v) {
    uint64_t r; asm("mov.b64 %0, {%1, %1};" : "=l"(r) : "f"(v)); return r;
}
static __device__ __forceinline__ uint64_t ffma2(uint64_t a, uint64_t b, uint64_t c) {
    uint64_t d; asm("fma.rn.f32x2 %0, %1, %2, %3;" : "=l"(d) : "l"(a), "l"(b), "l"(c)); return d;
}
static __device__ __forceinline__ float2 asf2(uint64_t v) {
    float2 f; memcpy(&f, &v, 8); return f;   // register-pair aliasing, no SASS op
}

__global__ __launch_bounds__(128, 4) void chamfer_kernel(
    const float* __restrict__ target,
    const float* __restrict__ reco,
    const int*   __restrict__ in_pid,
    const int*   __restrict__ out_pid,
    float*       __restrict__ out)
{
    // Full tile (256 pts = 128 pairs), pair-interleaved for f32x2:
    //  sA[p] = { (-2x_e0,-2x_e1), (-2y_e0,-2y_e1) }, sB = comps 2,3
    //  sc[p] = ( ||pt0||^2+pen0 , ||pt1||^2+pen1 )
    __shared__ ulonglong2 sA[NPTS/2], sB[NPTS/2];
    __shared__ uint64_t   sc[NPTS/2];
    __shared__ float      spm[2 * NPTS];   // partial row-mins per tile-half
    __shared__ float      srn2[NPTS];      // ||row||^2
    __shared__ int        smask[NPTS];     // row pid != 0
    __shared__ float4     red[128];
    __shared__ int        s_last;

    const int bid   = blockIdx.x;
    const int b     = bid >> 1;
    const int phase = bid & 1;   // 0: rows=target, tile=reco ; 1: rows=reco, tile=target
    const int t     = threadIdx.x;
    const int q     = t & 63;
    const int half  = t >> 6;    // which tile half this thread scans

    const float* tileSrc = phase == 0 ? reco    : target;
    const int*   tilePid = phase == 0 ? out_pid : in_pid;
    const float* rowSrc  = phase == 0 ? target  : reco;
    const int*   rowPid  = phase == 0 ? in_pid  : out_pid;

    const float4* tile4 = (const float4*)(tileSrc + (size_t)b * NPTS * ND);
    const float4* row4  = (const float4*)(rowSrc  + (size_t)b * NPTS * ND);
    const int*    tpid  = tilePid + b * NPTS;
    const int*    rpid  = rowPid  + b * NPTS;

    // ---- build tile (2 points per thread) ----
    #pragma unroll
    for (int k = 0; k < 2; ++k) {
        int i = t + k * 128;
        float4 v = tile4[i];
        int pid  = tpid[i];
        float n2 = v.x*v.x + v.y*v.y + v.z*v.z + v.w*v.w;
        int pair = i >> 1, lane = i & 1;
        ((float*)sA)[pair*4 + lane]     = -2.0f * v.x;
        ((float*)sA)[pair*4 + 2 + lane] = -2.0f * v.y;
        ((float*)sB)[pair*4 + lane]     = -2.0f * v.z;
        ((float*)sB)[pair*4 + 2 + lane] = -2.0f * v.w;
        ((float*)sc)[i] = n2 + (pid != 0 ? 0.0f : 1e20f);
    }

    // ---- own 4 rows: row = q + 64k (coalesced per k; both halves load same rows) ----
    uint64_t rx[4], ry[4], rz[4], rw[4];
    #pragma unroll
    for (int k = 0; k < 4; ++k) {
        int row = q + 64 * k;
        float4 v = row4[row];
        rx[k] = dup2(v.x); ry[k] = dup2(v.y); rz[k] = dup2(v.z); rw[k] = dup2(v.w);
        if (half == 0) {
            float n2 = v.x*v.x + v.y*v.y + v.z*v.z + v.w*v.w;
            srn2[row]  = n2;
            smask[row] = (rpid[row] != 0);
        }
    }

    __syncthreads();

    // ---- main loop: 64 pair-iters over this thread's tile half, 4 rows -> 8 dist/iter ----
    float dlo0 = 3.0e38f, dhi0 = 3.0e38f, dlo1 = 3.0e38f, dhi1 = 3.0e38f;
    float dlo2 = 3.0e38f, dhi2 = 3.0e38f, dlo3 = 3.0e38f, dhi3 = 3.0e38f;
    const int mbase = half * 64;
    #pragma unroll 8
    for (int mm = 0; mm < 64; ++mm) {
        int m = mbase + mm;
        ulonglong2 A = sA[m];      // broadcast LDS.128
        ulonglong2 B = sB[m];      // broadcast LDS.128
        uint64_t   c = sc[m];      // broadcast LDS.64

        uint64_t s0 = ffma2(A.x, rx[0], c);
        uint64_t s1 = ffma2(A.x, rx[1], c);
        uint64_t s2 = ffma2(A.x, rx[2], c);
        uint64_t s3 = ffma2(A.x, rx[3], c);
        s0 = ffma2(A.y, ry[0], s0);
        s1 = ffma2(A.y, ry[1], s1);
        s2 = ffma2(A.y, ry[2], s2);
        s3 = ffma2(A.y, ry[3], s3);
        s0 = ffma2(B.x, rz[0], s0);
        s1 = ffma2(B.x, rz[1], s1);
        s2 = ffma2(B.x, rz[2], s2);
        s3 = ffma2(B.x, rz[3], s3);
        s0 = ffma2(B.y, rw[0], s0);
        s1 = ffma2(B.y, rw[1], s1);
        s2 = ffma2(B.y, rw[2], s2);
        s3 = ffma2(B.y, rw[3], s3);

        float2 f0 = asf2(s0), f1 = asf2(s1), f2 = asf2(s2), f3 = asf2(s3);
        dlo0 = fminf(dlo0, f0.x); dhi0 = fminf(dhi0, f0.y);
        dlo1 = fminf(dlo1, f1.x); dhi1 = fminf(dhi1, f1.y);
        dlo2 = fminf(dlo2, f2.x); dhi2 = fminf(dhi2, f2.y);
        dlo3 = fminf(dlo3, f3.x); dhi3 = fminf(dhi3, f3.y);
    }

    // ---- store partial mins for this tile half ----
    spm[half * NPTS + q]       = fminf(dlo0, dhi0);
    spm[half * NPTS + q + 64]  = fminf(dlo1, dhi1);
    spm[half * NPTS + q + 128] = fminf(dlo2, dhi2);
    spm[half * NPTS + q + 192] = fminf(dlo3, dhi3);
    __syncthreads();

    // ---- combine halves: thread t handles rows t and t+128 ----
    const int ra = t, rb = t + 128;
    float da = fmaxf(fminf(spm[ra], spm[NPTS + ra]) + srn2[ra], 0.0f);
    float db = fmaxf(fminf(spm[rb], spm[NPTS + rb]) + srn2[rb], 0.0f);
    const int ma = smask[ra], mb = smask[rb];

    float sum_min = (ma ? sqrtf(da) : 0.0f) + (mb ? sqrtf(db) : 0.0f);
    float na = sqrtf(srn2[ra]), nbn = sqrtf(srn2[rb]);
    float sum_nrm;
    if (phase == 0)   // sum ||x|| over mask_x
        sum_nrm = (ma ? na : 0.0f) + (mb ? nbn : 0.0f);
    else              // sum ||y|| over ~mask_y
        sum_nrm = (ma ? 0.0f : na) + (mb ? 0.0f : nbn);
    float cnt = (float)(ma + mb);   // nx (phase 0) or ny (phase 1)

    // ---- block tree reduction ----
    red[t] = make_float4(sum_min, sum_nrm, cnt, 0.0f);
    __syncthreads();
    #pragma unroll
    for (int s = 64; s > 0; s >>= 1) {
        if (t < s) {
            float4 a = red[t], cc = red[t + s];
            a.x += cc.x; a.y += cc.y; a.z += cc.z;
            red[t] = a;
        }
        __syncthreads();
    }

    if (t == 0) {
        float4 r = red[0];
        g_sc[(phase*3 + 0) * NB + b] = r.x;
        g_sc[(phase*3 + 1) * NB + b] = r.y;
        g_sc[(phase*3 + 2) * NB + b] = r.z;
        __threadfence();
        int old = atomicAdd(&g_count, 1);
        s_last = (old == 2*NB - 1);
    }
    __syncthreads();

    // ---- last block: fused finalize ----
    if (s_last) {
        if (t == 0) { g_count = 0; __threadfence(); }
        __syncthreads();
        float acc0 = 0.0f, acc1 = 0.0f;
        #pragma unroll
        for (int k = 0; k < 2; ++k) {
            int bb = t + k * 128;
            float sum_xy    = __ldcg(&g_sc[0*NB + bb]);
            float sum_nrmx  = __ldcg(&g_sc[1*NB + bb]);
            float fnx       = __ldcg(&g_sc[2*NB + bb]);
            float sum_yx    = __ldcg(&g_sc[3*NB + bb]);
            float sum_nrmy0 = __ldcg(&g_sc[4*NB + bb]);
            float fny       = __ldcg(&g_sc[5*NB + bb]);
            float n_in  = fmaxf(1.0f, fnx);
            float n_out = fmaxf(1.0f, fny);
            float normal = 0.5f * (sum_xy / n_out + sum_yx / n_in);
            float e_nz = (fny == 0.0f) ? (sum_nrmx / n_in)
                       : ((fnx == 0.0f) ? 0.0f : normal);
            float e_z  = sum_nrmy0 / fmaxf(1.0f, (float)NPTS - fny);
            acc0 += e_nz;
            acc1 += e_z;
        }
        red[t] = make_float4(acc0, acc1, 0.0f, 0.0f);
        __syncthreads();
        #pragma unroll
        for (int s = 64; s > 0; s >>= 1) {
            if (t < s) {
                float4 a = red[t], cc = red[t + s];
                a.x += cc.x; a.y += cc.y;
                red[t] = a;
            }
            __syncthreads();
        }
        if (t == 0) {
            out[0] = red[0].x * (1.0f / NB);
            out[1] = red[0].y * (1.0f / NB);
        }
    }
}

extern "C" void kernel_launch(void* const* d_in, const int* in_sizes, int n_in,
                              void* d_out, int out_size)
{
    const float* target  = (const float*)d_in[0];
    const float* reco    = (const float*)d_in[1];
    const int*   in_pid  = (const int*)d_in[2];
    const int*   out_pid = (const int*)d_in[3];
    float* out = (float*)d_out;

    chamfer_kernel<<<2 * NB, 128>>>(target, reco, in_pid, out_pid, out);
}